// round 4
// baseline (speedup 1.0000x reference)
#include <cuda_runtime.h>
#include <cstdint>

// Problem constants (fixed by the dataset)
#define NB 8
#define NC 256
#define NH 80
#define NW 80
#define HW (NH*NW)            // 6400
#define OHW (160*160)         // 25600
#define TH 4                  // base rows per CTA
#define TW 16                 // base cols per CTA
#define NBP (TH*TW)           // 64 base pixels per CTA
#define NTHR 256

__device__ __forceinline__ unsigned long long pack2(float v) {
    unsigned long long r; unsigned u = __float_as_uint(v);
    asm("mov.b64 %0, {%1, %2};" : "=l"(r) : "r"(u), "r"(u));
    return r;
}
__device__ __forceinline__ unsigned long long ffma2(unsigned long long a,
                                                    unsigned long long b,
                                                    unsigned long long c) {
    unsigned long long d;
    asm("fma.rn.f32x2 %0, %1, %2, %3;" : "=l"(d) : "l"(a), "l"(b), "l"(c));
    return d;
}

__global__ __launch_bounds__(NTHR)
void adaptive_upsample_fused(const float* __restrict__ x,
                             const float* __restrict__ w_off,
                             const float* __restrict__ b_off,
                             float* __restrict__ out)
{
    // 32KB region A: first holds w_off packed as f32x2 channel-pairs,
    // later reused for sample coordinates (float2, pad-17 to dodge bank conflicts).
    __shared__ __align__(16) float sA[8192];
    // off results, padded 33 to avoid STS bank conflicts
    __shared__ float sOff[NBP*33 + 8];

    const int t  = threadIdx.x;
    const int b  = blockIdx.z;
    const int h0 = blockIdx.y * TH;
    const int w0 = blockIdx.x * TW;

    // ---- stage w_off into smem as pairs: sA[2*(c*16+p)] = w[2p][c], +1 = w[2p+1][c]
    #pragma unroll
    for (int k = 0; k < 16; k++) {
        int c = t;                    // coalesced over c within a warp
        int p = k;
        float lo = __ldg(w_off + (2*p)*256 + c);
        float hi = __ldg(w_off + (2*p+1)*256 + c);
        sA[2*(c*16+p)]   = lo;
        sA[2*(c*16+p)+1] = hi;
    }
    __syncthreads();

    // ---- phase 1: 1x1 conv (f32x2 packed). thread = (base pixel, o-chunk of 8)
    {
        const int oc = t >> 6;        // 0..3 -> output channels oc*8 .. oc*8+7
        const int bp = t & 63;
        const int hl = bp >> 4, wl = bp & 15;
        const float* xp = x + (size_t)b*NC*HW + (h0+hl)*NW + (w0+wl);
        const unsigned long long* wsh = (const unsigned long long*)sA;
        unsigned long long acc0=0ull, acc1=0ull, acc2=0ull, acc3=0ull;
        #pragma unroll 4
        for (int c = 0; c < NC; c++) {
            unsigned long long xx = pack2(__ldg(xp + c*HW));
            const unsigned long long* wr = wsh + c*16 + oc*4;
            acc0 = ffma2(xx, wr[0], acc0);
            acc1 = ffma2(xx, wr[1], acc1);
            acc2 = ffma2(xx, wr[2], acc2);
            acc3 = ffma2(xx, wr[3], acc3);
        }
        unsigned long long accs[4] = {acc0, acc1, acc2, acc3};
        #pragma unroll
        for (int p = 0; p < 4; p++) {
            int o0 = oc*8 + 2*p;
            sOff[bp*33 + o0]     = __uint_as_float((unsigned)(accs[p] & 0xffffffffull))
                                   + __ldg(b_off + o0);
            sOff[bp*33 + o0 + 1] = __uint_as_float((unsigned)(accs[p] >> 32))
                                   + __ldg(b_off + o0 + 1);
        }
    }
    __syncthreads();

    // ---- phase 1.5: sample coordinates into sA (w_off no longer needed)
    // offset channel for (gi,i,j): o_x = gi*4+i*2+j, o_y = o_x+16
    // ix = clamp(w + 0.25*off_x + h[j], 0, W-1), h = {-0.25,+0.25}; same for y with h[i].
    float2* crd = (float2*)sA;
    #pragma unroll
    for (int k = 0; k < 4; k++) {
        int task = t + k*256;                 // 1024 = 64 bp x 16 combos
        int cb = task & 15;
        int bp = task >> 4;
        int gi = cb >> 2, ii = (cb>>1)&1, jj = cb&1;
        int o  = gi*4 + ii*2 + jj;
        float ox = sOff[bp*33+o]    * 0.25f + (jj ? 0.25f : -0.25f);
        float oy = sOff[bp*33+o+16] * 0.25f + (ii ? 0.25f : -0.25f);
        float ix = fminf(fmaxf((float)(w0 + (bp & 15)) + ox, 0.0f), (float)(NW-1));
        float iy = fminf(fmaxf((float)(h0 + (bp >> 4)) + oy, 0.0f), (float)(NH-1));
        crd[bp*17 + cb] = make_float2(ix, iy);
    }
    __syncthreads();

    // ---- phase 2: bilinear gather, 64 channels per (output pixel, group)
    {
        const int warp = t >> 5, lane = t & 31;
        const int hl = warp >> 1, ii = warp & 1;
        const int wl = lane >> 1, jj = lane & 1;   // lanes cover 32 consecutive ow
        const int bp = hl*16 + wl;
        const int oh = 2*(h0+hl) + ii;
        const int ow = 2*(w0+wl) + jj;
        #pragma unroll
        for (int gi = 0; gi < 4; gi++) {
            float2 c2 = crd[bp*17 + gi*4 + ii*2 + jj];
            float fx0 = floorf(c2.x), fy0 = floorf(c2.y);
            float wx = c2.x - fx0, wy = c2.y - fy0;
            int x0 = (int)fx0, y0 = (int)fy0;
            int x1 = min(x0+1, NW-1), y1 = min(y0+1, NH-1);
            float w00 = (1.0f-wy)*(1.0f-wx), w01 = (1.0f-wy)*wx;
            float w10 = wy*(1.0f-wx),        w11 = wy*wx;
            const float* base = x + (size_t)(b*NC + gi*64)*HW;
            const float* p00 = base + y0*NW + x0;
            const float* p01 = base + y0*NW + x1;
            const float* p10 = base + y1*NW + x0;
            const float* p11 = base + y1*NW + x1;
            float* op = out + (size_t)(b*NC + gi*64)*OHW + oh*160 + ow;
            #pragma unroll 8
            for (int c = 0; c < 64; c++) {
                float v = __ldg(p00 + c*HW)*w00 + __ldg(p01 + c*HW)*w01
                        + __ldg(p10 + c*HW)*w10 + __ldg(p11 + c*HW)*w11;
                op[(size_t)c*OHW] = v;
            }
        }
    }
}

extern "C" void kernel_launch(void* const* d_in, const int* in_sizes, int n_in,
                              void* d_out, int out_size) {
    const float* x     = (const float*)d_in[0];
    const float* w_off = (const float*)d_in[1];
    const float* b_off = (const float*)d_in[2];
    float* out = (float*)d_out;
    dim3 grid(NW/TW, NH/TH, NB);   // 5 x 20 x 8 = 800 CTAs
    adaptive_upsample_fused<<<grid, NTHR>>>(x, w_off, b_off, out);
}

// round 6
// speedup vs baseline: 1.2295x; 1.2295x over previous
#include <cuda_runtime.h>
#include <cstdint>

// Problem constants (fixed by the dataset)
#define NB 8
#define NC 256
#define NH 80
#define NW 80
#define HW (NH*NW)            // 6400
#define OHW (160*160)         // 25600
#define TH 4                  // base rows per CTA
#define TW 16                 // base cols per CTA
#define NBP (TH*TW)           // 64 base pixels per CTA
#define NTHR 256

__device__ __forceinline__ unsigned long long pack2(float v) {
    unsigned long long r; unsigned u = __float_as_uint(v);
    asm("mov.b64 %0, {%1, %2};" : "=l"(r) : "r"(u), "r"(u));
    return r;
}
__device__ __forceinline__ unsigned long long ffma2(unsigned long long a,
                                                    unsigned long long b,
                                                    unsigned long long c) {
    unsigned long long d;
    asm("fma.rn.f32x2 %0, %1, %2, %3;" : "=l"(d) : "l"(a), "l"(b), "l"(c));
    return d;
}

__global__ __launch_bounds__(NTHR)
void adaptive_upsample_fused(const float* __restrict__ x,
                             const float* __restrict__ w_off,
                             const float* __restrict__ b_off,
                             float* __restrict__ out)
{
    // Single 32KB smem region, time-multiplexed:
    //  phase 0/1 : packed f32x2 weights (4096 pairs = 32KB)
    //  phase 1b  : sOff   = sA[0 .. 2110]              (stride 33)
    //  phase 1.5+: crd    = (float2*)(sA+2560), stride 17 pairs (ends at float 4732)
    __shared__ __align__(16) float sA[8192];

    const int t  = threadIdx.x;
    const int b  = blockIdx.z;
    const int h0 = blockIdx.y * TH;
    const int w0 = blockIdx.x * TW;

    // ---- stage w_off into smem as pairs: sA[2*(c*16+p)] = w[2p][c], +1 = w[2p+1][c]
    #pragma unroll
    for (int k = 0; k < 16; k++) {
        int c = t;                    // coalesced over c within a warp
        int p = k;
        float lo = __ldg(w_off + (2*p)*256 + c);
        float hi = __ldg(w_off + (2*p+1)*256 + c);
        sA[2*(c*16+p)]   = lo;
        sA[2*(c*16+p)+1] = hi;
    }
    __syncthreads();

    // ---- phase 1: 1x1 conv (f32x2 packed). thread = (base pixel, o-chunk of 8)
    const int oc = t >> 6;        // 0..3 -> output channels oc*8 .. oc*8+7
    const int bp = t & 63;
    unsigned long long accs[4];
    {
        const int hl = bp >> 4, wl = bp & 15;
        const float* xp = x + (size_t)b*NC*HW + (h0+hl)*NW + (w0+wl);
        const unsigned long long* wsh = (const unsigned long long*)sA;
        unsigned long long acc0=0ull, acc1=0ull, acc2=0ull, acc3=0ull;
        #pragma unroll 8
        for (int c = 0; c < NC; c++) {
            unsigned long long xx = pack2(__ldg(xp + c*HW));
            const unsigned long long* wr = wsh + c*16 + oc*4;
            acc0 = ffma2(xx, wr[0], acc0);
            acc1 = ffma2(xx, wr[1], acc1);
            acc2 = ffma2(xx, wr[2], acc2);
            acc3 = ffma2(xx, wr[3], acc3);
        }
        accs[0]=acc0; accs[1]=acc1; accs[2]=acc2; accs[3]=acc3;
    }
    __syncthreads();   // weights dead; safe to overwrite sA

    // ---- store conv results (+bias) into sA as sOff (stride 33)
    #pragma unroll
    for (int p = 0; p < 4; p++) {
        int o0 = oc*8 + 2*p;
        sA[bp*33 + o0]     = __uint_as_float((unsigned)(accs[p] & 0xffffffffull))
                             + __ldg(b_off + o0);
        sA[bp*33 + o0 + 1] = __uint_as_float((unsigned)(accs[p] >> 32))
                             + __ldg(b_off + o0 + 1);
    }
    __syncthreads();

    // ---- phase 1.5: sample coordinates into crd region (disjoint from sOff)
    // offset channel for (gi,i,j): o_x = gi*4+i*2+j, o_y = o_x+16
    // ix = clamp(w + 0.25*off_x + h[j], 0, W-1), h = {-0.25,+0.25}; same for y with h[i].
    float2* crd = (float2*)(sA + 2560);
    #pragma unroll
    for (int k = 0; k < 4; k++) {
        int task = t + k*256;                 // 1024 = 64 bp x 16 combos
        int cb = task & 15;
        int bpp = task >> 4;
        int gi = cb >> 2, ii = (cb>>1)&1, jj = cb&1;
        int o  = gi*4 + ii*2 + jj;
        float ox = sA[bpp*33+o]    * 0.25f + (jj ? 0.25f : -0.25f);
        float oy = sA[bpp*33+o+16] * 0.25f + (ii ? 0.25f : -0.25f);
        float ix = fminf(fmaxf((float)(w0 + (bpp & 15)) + ox, 0.0f), (float)(NW-1));
        float iy = fminf(fmaxf((float)(h0 + (bpp >> 4)) + oy, 0.0f), (float)(NH-1));
        crd[bpp*17 + cb] = make_float2(ix, iy);
    }
    __syncthreads();

    // ---- phase 2: bilinear gather, 64 channels per (output pixel, group).
    // Explicitly batch 8 channels' worth of loads (32 LDG) before computing,
    // to force high memory-level parallelism.
    {
        const int warp = t >> 5, lane = t & 31;
        const int hl = warp >> 1, ii = warp & 1;
        const int wl = lane >> 1, jj = lane & 1;   // lanes cover 32 consecutive ow
        const int bpx = hl*16 + wl;
        const int oh = 2*(h0+hl) + ii;
        const int ow = 2*(w0+wl) + jj;
        #pragma unroll
        for (int gi = 0; gi < 4; gi++) {
            float2 c2 = crd[bpx*17 + gi*4 + ii*2 + jj];
            float fx0 = floorf(c2.x), fy0 = floorf(c2.y);
            float wx = c2.x - fx0, wy = c2.y - fy0;
            int x0 = (int)fx0, y0 = (int)fy0;
            int x1 = min(x0+1, NW-1), y1 = min(y0+1, NH-1);
            float w00 = (1.0f-wy)*(1.0f-wx), w01 = (1.0f-wy)*wx;
            float w10 = wy*(1.0f-wx),        w11 = wy*wx;
            const float* base = x + (size_t)(b*NC + gi*64)*HW;
            const float* p00 = base + y0*NW + x0;
            const float* p01 = base + y0*NW + x1;
            const float* p10 = base + y1*NW + x0;
            const float* p11 = base + y1*NW + x1;
            float* op = out + (size_t)(b*NC + gi*64)*OHW + oh*160 + ow;
            #pragma unroll 1
            for (int cb = 0; cb < 64; cb += 8) {
                float a00[8], a01[8], a10[8], a11[8];
                #pragma unroll
                for (int u = 0; u < 8; u++) {
                    int c = cb + u;
                    a00[u] = __ldg(p00 + c*HW);
                    a01[u] = __ldg(p01 + c*HW);
                    a10[u] = __ldg(p10 + c*HW);
                    a11[u] = __ldg(p11 + c*HW);
                }
                #pragma unroll
                for (int u = 0; u < 8; u++) {
                    float v = a00[u]*w00 + a01[u]*w01 + a10[u]*w10 + a11[u]*w11;
                    op[(size_t)(cb+u)*OHW] = v;
                }
            }
        }
    }
}

extern "C" void kernel_launch(void* const* d_in, const int* in_sizes, int n_in,
                              void* d_out, int out_size) {
    const float* x     = (const float*)d_in[0];
    const float* w_off = (const float*)d_in[1];
    const float* b_off = (const float*)d_in[2];
    float* out = (float*)d_out;
    dim3 grid(NW/TW, NH/TH, NB);   // 5 x 20 x 8 = 800 CTAs
    adaptive_upsample_fused<<<grid, NTHR>>>(x, w_off, b_off, out);
}

// round 10
// speedup vs baseline: 1.3041x; 1.0607x over previous
#include <cuda_runtime.h>
#include <cstdint>

// Problem constants (fixed by the dataset)
#define NB 8
#define NC 256
#define NH 80
#define NW 80
#define HW (NH*NW)            // 6400
#define OHW (160*160)         // 25600
#define TH 4                  // base rows per CTA
#define TW 16                 // base cols per CTA
#define NBP (TH*TW)           // 64 base pixels per CTA
#define NTHR 256

typedef unsigned long long ull;

__device__ __forceinline__ ull pack2(float v) {
    ull r; unsigned u = __float_as_uint(v);
    asm("mov.b64 %0, {%1, %2};" : "=l"(r) : "r"(u), "r"(u));
    return r;
}
__device__ __forceinline__ ull packpair(float a, float b) {
    ull r;
    asm("mov.b64 %0, {%1, %2};" : "=l"(r) : "f"(a), "f"(b));
    return r;
}
__device__ __forceinline__ ull ffma2(ull a, ull b, ull c) {
    ull d;
    asm("fma.rn.f32x2 %0, %1, %2, %3;" : "=l"(d) : "l"(a), "l"(b), "l"(c));
    return d;
}
__device__ __forceinline__ ull mul2(ull a, ull b) {
    ull d;
    asm("mul.rn.f32x2 %0, %1, %2;" : "=l"(d) : "l"(a), "l"(b));
    return d;
}
__device__ __forceinline__ float hadd2(ull s) {
    float lo, hi;
    asm("mov.b64 {%0, %1}, %2;" : "=f"(lo), "=f"(hi) : "l"(s));
    return lo + hi;
}

__global__ __launch_bounds__(NTHR)
void adaptive_upsample_fused(const float* __restrict__ x,
                             const float* __restrict__ w_off,
                             const float* __restrict__ b_off,
                             float* __restrict__ out)
{
    // Single 32KB smem region, time-multiplexed:
    //  phase 0/1 : packed f32x2 weights (4096 pairs = 32KB)
    //  phase 1b  : sOff = sA[0..2110] (stride 33)
    //  phase 1.5+: crd  = (float2*)(sA+2560), stride 17 pairs
    __shared__ __align__(16) float sA[8192];

    const int t  = threadIdx.x;
    const int b  = blockIdx.z;
    const int h0 = blockIdx.y * TH;
    const int w0 = blockIdx.x * TW;

    // ---- stage w_off into smem as pairs: sA[2*(c*16+p)] = w[2p][c], +1 = w[2p+1][c]
    #pragma unroll
    for (int k = 0; k < 16; k++) {
        int c = t;
        int p = k;
        float lo = __ldg(w_off + (2*p)*256 + c);
        float hi = __ldg(w_off + (2*p+1)*256 + c);
        sA[2*(c*16+p)]   = lo;
        sA[2*(c*16+p)+1] = hi;
    }
    __syncthreads();

    // ---- phase 1: 1x1 conv (f32x2 packed), weights via LDS.128
    const int oc = t >> 6;
    const int bp = t & 63;
    ull accs[4];
    {
        const int hl = bp >> 4, wl = bp & 15;
        const float* xp = x + (size_t)b*NC*HW + (h0+hl)*NW + (w0+wl);
        const ull* wsh = (const ull*)sA;
        ull acc0=0ull, acc1=0ull, acc2=0ull, acc3=0ull;
        #pragma unroll 8
        for (int c = 0; c < NC; c++) {
            ull xx = pack2(__ldg(xp + c*HW));
            const ulonglong2* wr = (const ulonglong2*)(wsh + c*16 + oc*4);
            ulonglong2 wA = wr[0];
            ulonglong2 wB = wr[1];
            acc0 = ffma2(xx, wA.x, acc0);
            acc1 = ffma2(xx, wA.y, acc1);
            acc2 = ffma2(xx, wB.x, acc2);
            acc3 = ffma2(xx, wB.y, acc3);
        }
        accs[0]=acc0; accs[1]=acc1; accs[2]=acc2; accs[3]=acc3;
    }
    __syncthreads();   // weights dead; safe to overwrite sA

    // ---- store conv results (+bias) into sA as sOff (stride 33)
    #pragma unroll
    for (int p = 0; p < 4; p++) {
        int o0 = oc*8 + 2*p;
        sA[bp*33 + o0]     = __uint_as_float((unsigned)(accs[p] & 0xffffffffull))
                             + __ldg(b_off + o0);
        sA[bp*33 + o0 + 1] = __uint_as_float((unsigned)(accs[p] >> 32))
                             + __ldg(b_off + o0 + 1);
    }
    __syncthreads();

    // ---- phase 1.5: sample coordinates into crd region
    // offset channel for (gi,i,j): o_x = gi*4+i*2+j, o_y = o_x+16
    // ix = clamp(w + 0.25*off_x + h[j], 0, W-1), h = {-0.25,+0.25}; same for y with h[i].
    float2* crd = (float2*)(sA + 2560);
    #pragma unroll
    for (int k = 0; k < 4; k++) {
        int task = t + k*256;                 // 1024 = 64 bp x 16 combos
        int cb = task & 15;
        int bpp = task >> 4;
        int gi = cb >> 2, ii = (cb>>1)&1, jj = cb&1;
        int o  = gi*4 + ii*2 + jj;
        float ox = sA[bpp*33+o]    * 0.25f + (jj ? 0.25f : -0.25f);
        float oy = sA[bpp*33+o+16] * 0.25f + (ii ? 0.25f : -0.25f);
        float ix = fminf(fmaxf((float)(w0 + (bpp & 15)) + ox, 0.0f), (float)(NW-1));
        float iy = fminf(fmaxf((float)(h0 + (bpp >> 4)) + oy, 0.0f), (float)(NH-1));
        crd[bpp*17 + cb] = make_float2(ix, iy);
    }
    __syncthreads();

    // ---- phase 2: thread = (base pixel, group); computes ALL 4 upsampled
    // outputs per channel from a shared 3-row x 4-col window.
    // Window rows: max(h-1,0), h, min(h+1,79); cols: aligned even W0..W0+3
    // (second float2 clamped to col NW-2 at the right border; the duplicated
    //  values only ever carry zero weight there).
    {
        const int gi2 = t >> 6;          // uniform within a warp
        const int bp2 = t & 63;
        const int hl = bp2 >> 4, wl = bp2 & 15;
        const int h = h0 + hl, w = w0 + wl;
        const int Rm1 = (h > 0) ? h-1 : 0;
        const int Rp1 = (h < NH-1) ? h+1 : NH-1;
        int W0 = (w-1) & ~1; if (W0 < 0) W0 = 0;
        const int C2 = (W0 + 2 < NW - 1) ? W0 + 2 : NW - 2;

        // per-output weight vectors: alpha over 4 window cols (2 nonzero),
        // beta over 3 rows expressed in diff form (t = r1 + b0*(r0-r1) + b2*(r2-r1))
        ull A01[4], A23[4], B0[4], B2[4];
        #pragma unroll
        for (int k = 0; k < 4; k++) {
            float2 cc = crd[bp2*17 + gi2*4 + k];
            float fx = floorf(cc.x), fy = floorf(cc.y);
            int   x0 = (int)fx,      y0 = (int)fy;
            float wx = cc.x - fx,    wy = cc.y - fy;
            int   cbk = x0 - W0;                 // 0..2
            bool  e0 = (cbk == 0), e1 = (cbk == 1), e2 = (cbk == 2);
            float a0 = e0 ? 1.0f - wx : 0.0f;
            float a1 = e0 ? wx : (e1 ? 1.0f - wx : 0.0f);
            float a2 = e2 ? 1.0f - wx : (e1 ? wx : 0.0f);
            float a3 = e2 ? wx : 0.0f;
            bool  rb = (y0 < h);                 // y0 == h-1 ?
            float bb0 = rb ? 1.0f - wy : 0.0f;   // row h-1 weight
            float bb2 = rb ? 0.0f : wy;          // row h+1 weight
            A01[k] = packpair(a0, a1);
            A23[k] = packpair(a2, a3);
            B0[k]  = pack2(bb0);
            B2[k]  = pack2(bb2);
        }

        const float* xb = x + (size_t)(b*NC + gi2*64)*HW;
        const float* q0 = xb + Rm1*NW;
        const float* q1 = xb + h*NW;
        const float* q2 = xb + Rp1*NW;
        float* o0 = out + (size_t)(b*NC + gi2*64)*OHW + (size_t)(2*h)*160 + 2*w;
        float* o1 = o0 + 160;
        const ull mones = pack2(-1.0f);

        #pragma unroll 2
        for (int c = 0; c < 64; c++) {
            ull r0a = __ldg((const ull*)(q0 + W0));
            ull r0b = __ldg((const ull*)(q0 + C2));
            ull r1a = __ldg((const ull*)(q1 + W0));
            ull r1b = __ldg((const ull*)(q1 + C2));
            ull r2a = __ldg((const ull*)(q2 + W0));
            ull r2b = __ldg((const ull*)(q2 + C2));
            q0 += HW; q1 += HW; q2 += HW;

            ull d0a = ffma2(mones, r1a, r0a);   // r0 - r1
            ull d0b = ffma2(mones, r1b, r0b);
            ull d2a = ffma2(mones, r1a, r2a);   // r2 - r1
            ull d2b = ffma2(mones, r1b, r2b);

            float v[4];
            #pragma unroll
            for (int k = 0; k < 4; k++) {
                ull ta = ffma2(B2[k], d2a, ffma2(B0[k], d0a, r1a));
                ull tb = ffma2(B2[k], d2b, ffma2(B0[k], d0b, r1b));
                ull s  = ffma2(A23[k], tb, mul2(A01[k], ta));
                v[k] = hadd2(s);
            }
            *(ull*)o0 = packpair(v[0], v[1]);   // row 2h, cols 2w,2w+1
            *(ull*)o1 = packpair(v[2], v[3]);   // row 2h+1
            o0 += OHW; o1 += OHW;
        }
    }
}

extern "C" void kernel_launch(void* const* d_in, const int* in_sizes, int n_in,
                              void* d_out, int out_size) {
    const float* x     = (const float*)d_in[0];
    const float* w_off = (const float*)d_in[1];
    const float* b_off = (const float*)d_in[2];
    float* out = (float*)d_out;
    dim3 grid(NW/TW, NH/TH, NB);   // 5 x 20 x 8 = 800 CTAs
    adaptive_upsample_fused<<<grid, NTHR>>>(x, w_off, b_off, out);
}